// round 6
// baseline (speedup 1.0000x reference)
#include <cuda_runtime.h>

// MDN_module, fused single kernel, u64-packed f32x2 datapath.
// ReLU removed from hot loop via relu(p) = (p + |p|)/2 and precomputed linear term:
//   f_k = [b2_k + sum_j c'_jk b_j] + x0*sum_j c'_jk w0_j + x1*sum_j c'_jk w1_j
//         + sum_j c'_jk |pre_j| ,   c' = c/2
// Inputs: x[B,2] y[B,1,2] eps[B,1,2] W1[2,64] b1[64] W2[64,4] b2[4] Wv[2,2]
// Output: fx (2B floats) then logp_y scalar at out[2B].

typedef unsigned long long u64;

#define HID 64
#define PAIRS 2            // row-pairs per thread per group (4 rows/group)
#define NTHREADS 128
#define MAXBLK 2048

__device__ double g_part[MAXBLK];
__device__ unsigned g_ticket = 0;

__device__ __forceinline__ u64 ffma2(u64 a, u64 b, u64 c) {
    u64 d; asm("fma.rn.f32x2 %0, %1, %2, %3;" : "=l"(d) : "l"(a), "l"(b), "l"(c));
    return d;
}
__device__ __forceinline__ u64 pk2(float lo, float hi) {
    u64 r; asm("mov.b64 %0, {%1, %2};" : "=l"(r) : "f"(lo), "f"(hi)); return r;
}
__device__ __forceinline__ void upk2(float& lo, float& hi, u64 v) {
    asm("mov.b64 {%0, %1}, %2;" : "=f"(lo), "=f"(hi) : "l"(v));
}

// per-row epilogue: returns d0^2/v0 + d1^2/v1 + f2 + f3 ; writes fx0,fx1
__device__ __forceinline__ float row_tail(
    float x0, float x1, float mu0, float mu1, float f2, float f3,
    float y0, float y1, float e0, float e1,
    float wv00, float wv01, float wv10, float wv11,
    float& fx0, float& fx1)
{
    float z0 = fmaf(x0, wv00, x1 * wv10);
    float z1 = fmaf(x0, wv01, x1 * wv11);
    float Vx = fmaf(z0, z0, fmaf(z1, z1, 1e-3f));
    float m0 = fmaf(mu0, wv00, mu1 * wv10);
    float m1 = fmaf(mu0, wv01, mu1 * wv11);
    float Vmu = fmaf(m0, m0, fmaf(m1, m1, 1e-3f));
    float scale = __fdividef(fminf(0.99f * Vx, Vmu), Vmu);  // == beta*Vx - relu(...)
    float ms0 = mu0 * scale;
    float ms1 = mu1 * scale;
    float v0 = __expf(f2);
    float v1 = __expf(f3);
    float r0 = rsqrtf(v0);
    float r1 = rsqrtf(v1);
    fx0 = fmaf(v0 * r0, e0, ms0);
    fx1 = fmaf(v1 * r1, e1, ms1);
    float d0 = y0 - ms0;
    float d1 = y1 - ms1;
    float s = fmaf(d0 * d0, r0 * r0, f2 + f3);   // log v0 + log v1 == f2 + f3 exactly
    s = fmaf(d1 * d1, r1 * r1, s);
    return s;
}

__global__ void __launch_bounds__(NTHREADS, 8)
mdn_fused(const float4* __restrict__ x4, const float4* __restrict__ y4,
          const float4* __restrict__ e4,
          const float* __restrict__ W1, const float* __restrict__ b1,
          const float* __restrict__ W2, const float* __restrict__ b2,
          const float* __restrict__ Wv,
          float4* __restrict__ o4, float* __restrict__ out,
          int nGroups, long long B)
{
    // per-neuron packed weights (u64 pairs): [w0, w1, bb, c0', c1', c2', c3', pad]
    __shared__ u64 swq[HID][8];
    __shared__ float sprod[HID][12];     // per-neuron contributions to A/D
    __shared__ u64 sAB[12];              // A0k(0..3), A1k(4..7), Dk(8..11), duplicated pairs
    __shared__ double sred[NTHREADS];

    int t = threadIdx.x;
    if (t < HID) {
        float w0 = W1[t], w1 = W1[HID + t], b = b1[t];
        swq[t][0] = pk2(w0, w0);
        swq[t][1] = pk2(w1, w1);
        swq[t][2] = pk2(b, b);
#pragma unroll
        for (int k = 0; k < 4; k++) {
            float c = 0.5f * W2[t * 4 + k];        // c' = c/2
            swq[t][3 + k] = pk2(c, c);
            sprod[t][k]     = c * w0;              // -> A0k
            sprod[t][4 + k] = c * w1;              // -> A1k
            sprod[t][8 + k] = c * b;               // -> Dk (plus b2k)
        }
        swq[t][7] = 0ull;
    }
    __syncthreads();
    if (t < 12) {
        float s = 0.0f;
        for (int j = 0; j < HID; j++) s += sprod[j][t];   // deterministic serial order
        if (t >= 8) s += b2[t - 8];
        sAB[t] = pk2(s, s);
    }
    __syncthreads();

    float wv00 = Wv[0], wv01 = Wv[1], wv10 = Wv[2], wv11 = Wv[3];
    const u64 ABS2 = 0x7FFFFFFF7FFFFFFFULL;

    float lsum = 0.0f;
    int tid = blockIdx.x * blockDim.x + threadIdx.x;
    int stride = gridDim.x * blockDim.x;

    for (int g = tid; g < nGroups; g += stride) {
        int base = g * PAIRS;
        u64 X0[PAIRS], X1[PAIRS];
        u64 a0[PAIRS], a1[PAIRS], a2[PAIRS], a3[PAIRS];
#pragma unroll
        for (int p = 0; p < PAIRS; p++) {
            float4 xv = x4[base + p];              // {x0_a, x1_a, x0_b, x1_b}
            X0[p] = pk2(xv.x, xv.z);
            X1[p] = pk2(xv.y, xv.w);
            // init with linear term: a_k = Dk + x0*A0k + x1*A1k
            a0[p] = ffma2(X0[p], sAB[0], ffma2(X1[p], sAB[4], sAB[8]));
            a1[p] = ffma2(X0[p], sAB[1], ffma2(X1[p], sAB[5], sAB[9]));
            a2[p] = ffma2(X0[p], sAB[2], ffma2(X1[p], sAB[6], sAB[10]));
            a3[p] = ffma2(X0[p], sAB[3], ffma2(X1[p], sAB[7], sAB[11]));
        }

#pragma unroll 8
        for (int j = 0; j < HID; j++) {
            const ulonglong2* row = (const ulonglong2*)swq[j];
            ulonglong2 q0 = row[0];                // {w0, w1}
            ulonglong2 q1 = row[1];                // {bb, c0'}
            ulonglong2 q2 = row[2];                // {c1', c2'}
            ulonglong2 q3 = row[3];                // {c3', pad}
#pragma unroll
            for (int p = 0; p < PAIRS; p++) {
                u64 pre = ffma2(X1[p], q0.y, q1.x);
                pre = ffma2(X0[p], q0.x, pre);
                u64 h = pre & ABS2;                // |pre| on both halves: 2x LOP3
                a0[p] = ffma2(h, q1.y, a0[p]);
                a1[p] = ffma2(h, q2.x, a1[p]);
                a2[p] = ffma2(h, q2.y, a2[p]);
                a3[p] = ffma2(h, q3.x, a3[p]);
            }
        }

#pragma unroll
        for (int p = 0; p < PAIRS; p++) {
            float f0a, f0b, f1a, f1b, f2a, f2b, f3a, f3b;
            upk2(f0a, f0b, a0[p]);
            upk2(f1a, f1b, a1[p]);
            upk2(f2a, f2b, a2[p]);
            upk2(f3a, f3b, a3[p]);
            float x0a, x0b, x1a, x1b;
            upk2(x0a, x0b, X0[p]);
            upk2(x1a, x1b, X1[p]);
            float4 yv = y4[base + p];
            float4 ev = e4[base + p];
            float fa0, fa1, fb0, fb1;
            lsum += row_tail(x0a, x1a, f0a, f1a, f2a, f3a, yv.x, yv.y, ev.x, ev.y,
                             wv00, wv01, wv10, wv11, fa0, fa1);
            lsum += row_tail(x0b, x1b, f0b, f1b, f2b, f3b, yv.z, yv.w, ev.z, ev.w,
                             wv00, wv01, wv10, wv11, fb0, fb1);
            float4 o; o.x = fa0; o.y = fa1; o.z = fb0; o.w = fb1;
            o4[base + p] = o;
        }
    }

    // tail rows (none for B = 2^21; kept for safety)
    long long startRow = (long long)nGroups * (2 * PAIRS);
    if (blockIdx.x == 0 && startRow + threadIdx.x < B) {
        long long r = startRow + threadIdx.x;
        const float* x = (const float*)x4;
        const float* y = (const float*)y4;
        const float* e = (const float*)e4;
        float x0 = x[2 * r], x1 = x[2 * r + 1];
        float f0 = b2[0], f1 = b2[1], f2 = b2[2], f3 = b2[3];
        for (int j = 0; j < HID; j++) {
            float h = fmaxf(fmaf(x0, W1[j], fmaf(x1, W1[HID + j], b1[j])), 0.0f);
            f0 = fmaf(h, W2[j * 4 + 0], f0);
            f1 = fmaf(h, W2[j * 4 + 1], f1);
            f2 = fmaf(h, W2[j * 4 + 2], f2);
            f3 = fmaf(h, W2[j * 4 + 3], f3);
        }
        float fx0, fx1;
        lsum += row_tail(x0, x1, f0, f1, f2, f3,
                         y[2 * r], y[2 * r + 1], e[2 * r], e[2 * r + 1],
                         wv00, wv01, wv10, wv11, fx0, fx1);
        ((float*)o4)[2 * r] = fx0;
        ((float*)o4)[2 * r + 1] = fx1;
    }

    // deterministic block tree reduction -> per-block double partial
    sred[threadIdx.x] = (double)lsum;
    __syncthreads();
#pragma unroll
    for (int off = NTHREADS / 2; off > 0; off >>= 1) {
        if (threadIdx.x < off) sred[threadIdx.x] += sred[threadIdx.x + off];
        __syncthreads();
    }
    if (threadIdx.x == 0) g_part[blockIdx.x] = sred[0];

    // last-block finalize
    __shared__ bool is_last;
    __threadfence();
    if (threadIdx.x == 0) {
        unsigned prev = atomicAdd(&g_ticket, 1u);
        is_last = (prev == gridDim.x - 1);
    }
    __syncthreads();
    if (is_last) {
        double v = 0.0;
        for (int i = threadIdx.x; i < gridDim.x; i += NTHREADS) v += g_part[i];
        sred[threadIdx.x] = v;
        __syncthreads();
#pragma unroll
        for (int off = NTHREADS / 2; off > 0; off >>= 1) {
            if (threadIdx.x < off) sred[threadIdx.x] += sred[threadIdx.x + off];
            __syncthreads();
        }
        if (threadIdx.x == 0) {
            out[2 * B] = (float)(0.5 * sred[0] + (double)B * 1.8378770664093453);
            g_ticket = 0;   // reset for next graph replay
        }
    }
}

extern "C" void kernel_launch(void* const* d_in, const int* in_sizes, int n_in,
                              void* d_out, int out_size)
{
    const float* x  = (const float*)d_in[0];
    const float* y  = (const float*)d_in[1];
    const float* e  = (const float*)d_in[2];
    const float* W1 = (const float*)d_in[3];
    const float* b1 = (const float*)d_in[4];
    const float* W2 = (const float*)d_in[5];
    const float* b2 = (const float*)d_in[6];
    const float* Wv = (const float*)d_in[7];
    float* out = (float*)d_out;

    long long B = (long long)in_sizes[0] / 2;
    int nGroups = (int)(B / (2 * PAIRS));

    int blocks = 152 * 8;                // persistent, 8 blocks/SM target
    if (blocks > MAXBLK) blocks = MAXBLK;

    mdn_fused<<<blocks, NTHREADS>>>((const float4*)x, (const float4*)y,
                                    (const float4*)e, W1, b1, W2, b2, Wv,
                                    (float4*)out, out, nGroups, B);
}

// round 8
// speedup vs baseline: 1.0324x; 1.0324x over previous
#include <cuda_runtime.h>

// MDN_module, fused single kernel. Hot loop = one monolithic asm block per
// (neuron, row-pair): 6x fma.rn.f32x2 + add.rn.f32x2 + and.b64, "+l" accumulators
// so no interface MOVs. relu(p) = (p+|p|)/2 with the /2 folded into W2.
// Inputs: x[B,2] y[B,1,2] eps[B,1,2] W1[2,64] b1[64] W2[64,4] b2[4] Wv[2,2]
// Output: fx (2B floats) then logp_y scalar at out[2B].

typedef unsigned long long u64;

#define HID 64
#define PAIRS 4            // row-pairs per thread per group (8 rows/group)
#define NTHREADS 128
#define MAXBLK 2048

__device__ double g_part[MAXBLK];
__device__ unsigned g_ticket = 0;

__device__ __forceinline__ u64 pk2(float lo, float hi) {
    u64 r; asm("mov.b64 %0, {%1, %2};" : "=l"(r) : "f"(lo), "f"(hi)); return r;
}
__device__ __forceinline__ void upk2(float& lo, float& hi, u64 v) {
    asm("mov.b64 {%0, %1}, %2;" : "=f"(lo), "=f"(hi) : "l"(v));
}

// one neuron, one row-pair: a_k += c'_k * (p + |p|), p = x0*w0 + x1*w1 + b
__device__ __forceinline__ void mlp_step(
    u64& a0, u64& a1, u64& a2, u64& a3,
    u64 X0, u64 X1,
    u64 w0, u64 w1, u64 bb, u64 c0, u64 c1, u64 c2, u64 c3)
{
    asm("{\n\t"
        ".reg .b64 p, q;\n\t"
        "fma.rn.f32x2 p, %5, %7, %8;\n\t"     // x1*w1 + b
        "fma.rn.f32x2 p, %4, %6, p;\n\t"      // + x0*w0
        "and.b64 q, p, 0x7FFFFFFF7FFFFFFF;\n\t" // |p| both halves
        "add.rn.f32x2 p, p, q;\n\t"           // 2*relu(p)
        "fma.rn.f32x2 %0, p, %9,  %0;\n\t"
        "fma.rn.f32x2 %1, p, %10, %1;\n\t"
        "fma.rn.f32x2 %2, p, %11, %2;\n\t"
        "fma.rn.f32x2 %3, p, %12, %3;\n\t"
        "}"
        : "+l"(a0), "+l"(a1), "+l"(a2), "+l"(a3)
        : "l"(X0), "l"(X1), "l"(w0), "l"(w1), "l"(bb),
          "l"(c0), "l"(c1), "l"(c2), "l"(c3));
}

// per-row epilogue: returns d0^2/v0 + d1^2/v1 + f2 + f3 ; writes fx0,fx1
__device__ __forceinline__ float row_tail(
    float x0, float x1, float mu0, float mu1, float f2, float f3,
    float y0, float y1, float e0, float e1,
    float wv00, float wv01, float wv10, float wv11,
    float& fx0, float& fx1)
{
    float z0 = fmaf(x0, wv00, x1 * wv10);
    float z1 = fmaf(x0, wv01, x1 * wv11);
    float Vx = fmaf(z0, z0, fmaf(z1, z1, 1e-3f));
    float m0 = fmaf(mu0, wv00, mu1 * wv10);
    float m1 = fmaf(mu0, wv01, mu1 * wv11);
    float Vmu = fmaf(m0, m0, fmaf(m1, m1, 1e-3f));
    float scale = __fdividef(fminf(0.99f * Vx, Vmu), Vmu);  // == beta*Vx - relu(...)
    float ms0 = mu0 * scale;
    float ms1 = mu1 * scale;
    float v0 = __expf(f2);
    float v1 = __expf(f3);
    float r0 = rsqrtf(v0);
    float r1 = rsqrtf(v1);
    fx0 = fmaf(v0 * r0, e0, ms0);
    fx1 = fmaf(v1 * r1, e1, ms1);
    float d0 = y0 - ms0;
    float d1 = y1 - ms1;
    float s = fmaf(d0 * d0, r0 * r0, f2 + f3);   // log v0 + log v1 == f2 + f3 exactly
    s = fmaf(d1 * d1, r1 * r1, s);
    return s;
}

__global__ void __launch_bounds__(NTHREADS, 5)
mdn_fused(const float4* __restrict__ x4, const float4* __restrict__ y4,
          const float4* __restrict__ e4,
          const float* __restrict__ W1, const float* __restrict__ b1,
          const float* __restrict__ W2, const float* __restrict__ b2,
          const float* __restrict__ Wv,
          float4* __restrict__ o4, float* __restrict__ out,
          int nGroups, long long B)
{
    // per-neuron packed weights (u64 pairs): [w0, w1, bb, c0', c1', c2', c3', pad]
    __shared__ u64 swq[HID][8];
    __shared__ double sred[NTHREADS];

    int t = threadIdx.x;
    if (t < HID) {
        float w0 = W1[t], w1 = W1[HID + t], b = b1[t];
        swq[t][0] = pk2(w0, w0);
        swq[t][1] = pk2(w1, w1);
        swq[t][2] = pk2(b, b);
#pragma unroll
        for (int k = 0; k < 4; k++) {
            float c = 0.5f * W2[t * 4 + k];        // fold relu's /2 into W2
            swq[t][3 + k] = pk2(c, c);
        }
        swq[t][7] = 0ull;
    }
    __syncthreads();

    float wv00 = Wv[0], wv01 = Wv[1], wv10 = Wv[2], wv11 = Wv[3];
    u64 pb0 = pk2(b2[0], b2[0]);
    u64 pb1 = pk2(b2[1], b2[1]);
    u64 pb2_ = pk2(b2[2], b2[2]);
    u64 pb3 = pk2(b2[3], b2[3]);

    float lsum = 0.0f;
    int tid = blockIdx.x * blockDim.x + threadIdx.x;
    int stride = gridDim.x * blockDim.x;

    for (int g = tid; g < nGroups; g += stride) {
        int base = g * PAIRS;
        u64 X0[PAIRS], X1[PAIRS];
        u64 a0[PAIRS], a1[PAIRS], a2[PAIRS], a3[PAIRS];
#pragma unroll
        for (int p = 0; p < PAIRS; p++) {
            float4 xv = x4[base + p];              // {x0_a, x1_a, x0_b, x1_b}
            X0[p] = pk2(xv.x, xv.z);
            X1[p] = pk2(xv.y, xv.w);
            a0[p] = pb0; a1[p] = pb1; a2[p] = pb2_; a3[p] = pb3;
        }

#pragma unroll 8
        for (int j = 0; j < HID; j++) {
            const ulonglong2* row = (const ulonglong2*)swq[j];
            ulonglong2 q0 = row[0];                // {w0, w1}
            ulonglong2 q1 = row[1];                // {bb, c0'}
            ulonglong2 q2 = row[2];                // {c1', c2'}
            ulonglong2 q3 = row[3];                // {c3', pad}
#pragma unroll
            for (int p = 0; p < PAIRS; p++) {
                mlp_step(a0[p], a1[p], a2[p], a3[p], X0[p], X1[p],
                         q0.x, q0.y, q1.x, q1.y, q2.x, q2.y, q3.x);
            }
        }

#pragma unroll
        for (int p = 0; p < PAIRS; p++) {
            float f0a, f0b, f1a, f1b, f2a, f2b, f3a, f3b;
            upk2(f0a, f0b, a0[p]);
            upk2(f1a, f1b, a1[p]);
            upk2(f2a, f2b, a2[p]);
            upk2(f3a, f3b, a3[p]);
            float x0a, x0b, x1a, x1b;
            upk2(x0a, x0b, X0[p]);
            upk2(x1a, x1b, X1[p]);
            float4 yv = y4[base + p];
            float4 ev = e4[base + p];
            float fa0, fa1, fb0, fb1;
            lsum += row_tail(x0a, x1a, f0a, f1a, f2a, f3a, yv.x, yv.y, ev.x, ev.y,
                             wv00, wv01, wv10, wv11, fa0, fa1);
            lsum += row_tail(x0b, x1b, f0b, f1b, f2b, f3b, yv.z, yv.w, ev.z, ev.w,
                             wv00, wv01, wv10, wv11, fb0, fb1);
            float4 o; o.x = fa0; o.y = fa1; o.z = fb0; o.w = fb1;
            o4[base + p] = o;
        }
    }

    // tail rows (none for B = 2^21; kept for safety)
    long long startRow = (long long)nGroups * (2 * PAIRS);
    if (blockIdx.x == 0 && startRow + threadIdx.x < B) {
        long long r = startRow + threadIdx.x;
        const float* x = (const float*)x4;
        const float* y = (const float*)y4;
        const float* e = (const float*)e4;
        float x0 = x[2 * r], x1 = x[2 * r + 1];
        float f0 = b2[0], f1 = b2[1], f2 = b2[2], f3 = b2[3];
        for (int j = 0; j < HID; j++) {
            float h = fmaxf(fmaf(x0, W1[j], fmaf(x1, W1[HID + j], b1[j])), 0.0f);
            f0 = fmaf(h, W2[j * 4 + 0], f0);
            f1 = fmaf(h, W2[j * 4 + 1], f1);
            f2 = fmaf(h, W2[j * 4 + 2], f2);
            f3 = fmaf(h, W2[j * 4 + 3], f3);
        }
        float fx0, fx1;
        lsum += row_tail(x0, x1, f0, f1, f2, f3,
                         y[2 * r], y[2 * r + 1], e[2 * r], e[2 * r + 1],
                         wv00, wv01, wv10, wv11, fx0, fx1);
        ((float*)o4)[2 * r] = fx0;
        ((float*)o4)[2 * r + 1] = fx1;
    }

    // deterministic block tree reduction -> per-block double partial
    sred[threadIdx.x] = (double)lsum;
    __syncthreads();
#pragma unroll
    for (int off = NTHREADS / 2; off > 0; off >>= 1) {
        if (threadIdx.x < off) sred[threadIdx.x] += sred[threadIdx.x + off];
        __syncthreads();
    }
    if (threadIdx.x == 0) g_part[blockIdx.x] = sred[0];

    // last-block finalize
    __shared__ bool is_last;
    __threadfence();
    if (threadIdx.x == 0) {
        unsigned prev = atomicAdd(&g_ticket, 1u);
        is_last = (prev == gridDim.x - 1);
    }
    __syncthreads();
    if (is_last) {
        double v = 0.0;
        for (int i = threadIdx.x; i < gridDim.x; i += NTHREADS) v += g_part[i];
        sred[threadIdx.x] = v;
        __syncthreads();
#pragma unroll
        for (int off = NTHREADS / 2; off > 0; off >>= 1) {
            if (threadIdx.x < off) sred[threadIdx.x] += sred[threadIdx.x + off];
            __syncthreads();
        }
        if (threadIdx.x == 0) {
            out[2 * B] = (float)(0.5 * sred[0] + (double)B * 1.8378770664093453);
            g_ticket = 0;   // reset for next graph replay
        }
    }
}

extern "C" void kernel_launch(void* const* d_in, const int* in_sizes, int n_in,
                              void* d_out, int out_size)
{
    const float* x  = (const float*)d_in[0];
    const float* y  = (const float*)d_in[1];
    const float* e  = (const float*)d_in[2];
    const float* W1 = (const float*)d_in[3];
    const float* b1 = (const float*)d_in[4];
    const float* W2 = (const float*)d_in[5];
    const float* b2 = (const float*)d_in[6];
    const float* Wv = (const float*)d_in[7];
    float* out = (float*)d_out;

    long long B = (long long)in_sizes[0] / 2;
    int nGroups = (int)(B / (2 * PAIRS));

    int blocks = 152 * 5;                // persistent, 5 blocks/SM target
    if (blocks > MAXBLK) blocks = MAXBLK;

    mdn_fused<<<blocks, NTHREADS>>>((const float4*)x, (const float4*)y,
                                    (const float4*)e, W1, b1, W2, b2, Wv,
                                    (float4*)out, out, nGroups, B);
}

// round 10
// speedup vs baseline: 2.4123x; 2.3365x over previous
#include <cuda_runtime.h>

// MDN_module — sector-table kernel.
// Since b1 == 0 in this dataset, pre_j = w_j . x : all 64 ReLU hinges pass
// through the origin, so sign(pre_j) depends only on direction(x).
// The MLP is exactly piecewise-linear over <=128 angular sectors:
//   f_k(x) = b2_k + A_s[k][0]*x0 + A_s[k][1]*x1 ,
//   A_s = sum_{j : w_j.u_s > 0} c_jk * w_j  (precomputed per block).
// Direction lookup uses the diamond pseudo-angle (monotone in angle, no atan2)
// + a 512-entry bucket table + sorted-boundary refinement.
// A uniform fallback path handles b1 != 0 (never taken on this dataset).
// Inputs: x[B,2] y[B,1,2] eps[B,1,2] W1[2,64] b1[64] W2[64,4] b2[4] Wv[2,2]
// Output: fx (2B floats) then logp_y scalar at out[2B].

#define NT 512
#define MAXBLK 2048
#define NBUCKET 512

__device__ double g_part[MAXBLK];
__device__ unsigned g_ticket = 0;

__device__ __forceinline__ float pangle(float x0, float x1) {
    float t = __fdividef(x1, fabsf(x0) + fabsf(x1));
    return (x0 >= 0.0f) ? t : 2.0f - t;
}

// per-row epilogue: returns d0^2/v0 + d1^2/v1 + f2 + f3 ; writes fx0,fx1
__device__ __forceinline__ float row_tail(
    float x0, float x1, float mu0, float mu1, float f2, float f3,
    float y0, float y1, float e0, float e1,
    float wv00, float wv01, float wv10, float wv11,
    float& fx0, float& fx1)
{
    float z0 = fmaf(x0, wv00, x1 * wv10);
    float z1 = fmaf(x0, wv01, x1 * wv11);
    float Vx = fmaf(z0, z0, fmaf(z1, z1, 1e-3f));
    float m0 = fmaf(mu0, wv00, mu1 * wv10);
    float m1 = fmaf(mu0, wv01, mu1 * wv11);
    float Vmu = fmaf(m0, m0, fmaf(m1, m1, 1e-3f));
    float scale = __fdividef(fminf(0.99f * Vx, Vmu), Vmu);  // == beta*Vx - relu(...)
    float ms0 = mu0 * scale;
    float ms1 = mu1 * scale;
    float v0 = __expf(f2);
    float v1 = __expf(f3);
    float r0 = rsqrtf(v0);
    float r1 = rsqrtf(v1);
    fx0 = fmaf(v0 * r0, e0, ms0);
    fx1 = fmaf(v1 * r1, e1, ms1);
    float d0 = y0 - ms0;
    float d1 = y1 - ms1;
    float s = fmaf(d0 * d0, r0 * r0, f2 + f3);   // log v0 + log v1 == f2 + f3 exactly
    s = fmaf(d1 * d1, r1 * r1, s);
    return s;
}

__global__ void __launch_bounds__(NT, 2)
mdn_fused(const float4* __restrict__ x4, const float4* __restrict__ y4,
          const float4* __restrict__ e4,
          const float* __restrict__ W1, const float* __restrict__ b1,
          const float* __restrict__ W2, const float* __restrict__ b2,
          const float* __restrict__ Wv,
          float4* __restrict__ o4, float* __restrict__ out,
          int nPair, long long B)
{
    __shared__ float sBound[129];          // sorted boundary pseudo-angles + INF sentinel
    __shared__ float4 sA[128][2];          // per-sector affine maps (4 outputs x 2 inputs)
    __shared__ unsigned char sBkt[NBUCKET];// bucket -> count of boundaries <= left edge
    __shared__ float sP[128];
    __shared__ float sw0[64], sw1[64];
    __shared__ float sc[64][4];
    __shared__ int sFast;
    __shared__ double sred[NT];

    int t = threadIdx.x;
    if (t == 0) sFast = 1;
    __syncthreads();
    if (t < 64) {
        float w0 = W1[t], w1 = W1[64 + t];
        sw0[t] = w0; sw1[t] = w1;
#pragma unroll
        for (int k = 0; k < 4; k++) sc[t][k] = W2[t * 4 + k];
        float pa = pangle(-w1, w0);        // hinge-line directions (perp to w)
        float pb = pangle(w1, -w0);
        if (!(pa == pa)) pa = -1.0f;       // degenerate w==0: harmless duplicate boundary
        if (!(pb == pb)) pb = -1.0f;
        sP[t] = pa; sP[64 + t] = pb;
        if (b1[t] != 0.0f) sFast = 0;      // benign race, all writers write 0
    }
    __syncthreads();
    if (t < 128) {                          // rank sort (ties broken by index)
        float p = sP[t];
        int rank = 0;
        for (int i = 0; i < 128; i++) {
            float pi = sP[i];
            rank += (pi < p) || (pi == p && i < t);
        }
        sBound[rank] = p;
    }
    if (t == 0) sBound[128] = __int_as_float(0x7F800000);   // +INF sentinel
    __syncthreads();
    if (t < 128) {                          // per-sector affine map from midpoint dir
        float p0 = sBound[t];
        float p1 = (t < 127) ? sBound[t + 1] : (sBound[0] + 4.0f);
        float pm = 0.5f * (p0 + p1);
        if (pm >= 3.0f) pm -= 4.0f;
        float u0, u1;                       // inverse diamond map
        if (pm <= 1.0f) { u1 = pm;        u0 = 1.0f - fabsf(pm); }
        else            { u1 = 2.0f - pm; u0 = fabsf(2.0f - pm) - 1.0f; }
        float A00 = 0, A01 = 0, A10 = 0, A11 = 0;
        float A20 = 0, A21 = 0, A30 = 0, A31 = 0;
        for (int j = 0; j < 64; j++) {
            float w0 = sw0[j], w1 = sw1[j];
            float m = (fmaf(u0, w0, u1 * w1) > 0.0f) ? 1.0f : 0.0f;
            float c0 = sc[j][0] * m, c1 = sc[j][1] * m;
            float c2 = sc[j][2] * m, c3 = sc[j][3] * m;
            A00 = fmaf(c0, w0, A00); A01 = fmaf(c0, w1, A01);
            A10 = fmaf(c1, w0, A10); A11 = fmaf(c1, w1, A11);
            A20 = fmaf(c2, w0, A20); A21 = fmaf(c2, w1, A21);
            A30 = fmaf(c3, w0, A30); A31 = fmaf(c3, w1, A31);
        }
        sA[t][0] = make_float4(A00, A01, A10, A11);
        sA[t][1] = make_float4(A20, A21, A30, A31);
    }
    __syncthreads();
    for (int q = t; q < NBUCKET; q += NT) { // bucket table
        float edge = -1.0f + (4.0f / NBUCKET) * (float)q;
        int cnt = 0;
        for (int i = 0; i < 128; i++) cnt += (sBound[i] <= edge) ? 1 : 0;
        sBkt[q] = (unsigned char)cnt;
    }
    __syncthreads();

    float B20 = b2[0], B21 = b2[1], B22 = b2[2], B23 = b2[3];
    float wv00 = Wv[0], wv01 = Wv[1], wv10 = Wv[2], wv11 = Wv[3];

    float lsum = 0.0f;
    int gtid = blockIdx.x * NT + t;
    int gstride = gridDim.x * NT;

    if (sFast) {
        for (int i = gtid; i < nPair; i += gstride) {
            float4 xv = x4[i];
            float4 yv = y4[i];
            float4 ev = e4[i];
            float4 o;
#pragma unroll
            for (int h = 0; h < 2; h++) {
                float x0 = h ? xv.z : xv.x;
                float x1 = h ? xv.w : xv.y;
                float y0 = h ? yv.z : yv.x;
                float y1 = h ? yv.w : yv.y;
                float e0 = h ? ev.z : ev.x;
                float e1 = h ? ev.w : ev.y;
                float p = pangle(x0, x1);
                int q = (int)((p + 1.0f) * (NBUCKET / 4.0f));
                q = min(max(q, 0), NBUCKET - 1);
                int c = sBkt[q];
                while (sBound[c] <= p) c++;        // sentinel bounds c <= 128
                int s = (c == 0) ? 127 : c - 1;
                float4 Aa = sA[s][0];
                float4 Ab = sA[s][1];
                float mu0 = fmaf(Aa.x, x0, fmaf(Aa.y, x1, B20));
                float mu1 = fmaf(Aa.z, x0, fmaf(Aa.w, x1, B21));
                float f2  = fmaf(Ab.x, x0, fmaf(Ab.y, x1, B22));
                float f3  = fmaf(Ab.z, x0, fmaf(Ab.w, x1, B23));
                float fx0, fx1;
                lsum += row_tail(x0, x1, mu0, mu1, f2, f3, y0, y1, e0, e1,
                                 wv00, wv01, wv10, wv11, fx0, fx1);
                if (h) { o.z = fx0; o.w = fx1; } else { o.x = fx0; o.y = fx1; }
            }
            o4[i] = o;
        }
        // odd tail row (B even here; safety)
        long long start = 2LL * nPair;
        if (blockIdx.x == 0 && start + t < B) {
            long long r = start + t;
            const float* x = (const float*)x4;
            const float* y = (const float*)y4;
            const float* e = (const float*)e4;
            float x0 = x[2 * r], x1 = x[2 * r + 1];
            float p = pangle(x0, x1);
            int q = (int)((p + 1.0f) * (NBUCKET / 4.0f));
            q = min(max(q, 0), NBUCKET - 1);
            int c = sBkt[q];
            while (sBound[c] <= p) c++;
            int s = (c == 0) ? 127 : c - 1;
            float4 Aa = sA[s][0];
            float4 Ab = sA[s][1];
            float mu0 = fmaf(Aa.x, x0, fmaf(Aa.y, x1, B20));
            float mu1 = fmaf(Aa.z, x0, fmaf(Aa.w, x1, B21));
            float f2  = fmaf(Ab.x, x0, fmaf(Ab.y, x1, B22));
            float f3  = fmaf(Ab.z, x0, fmaf(Ab.w, x1, B23));
            float fx0, fx1;
            lsum += row_tail(x0, x1, mu0, mu1, f2, f3,
                             y[2 * r], y[2 * r + 1], e[2 * r], e[2 * r + 1],
                             wv00, wv01, wv10, wv11, fx0, fx1);
            ((float*)o4)[2 * r] = fx0;
            ((float*)o4)[2 * r + 1] = fx1;
        }
    } else {
        // general path (b1 != 0): exact scalar MLP per row. Never taken on this dataset.
        const float* x = (const float*)x4;
        const float* y = (const float*)y4;
        const float* e = (const float*)e4;
        for (long long r = gtid; r < B; r += gstride) {
            float x0 = x[2 * r], x1 = x[2 * r + 1];
            float f0 = B20, f1 = B21, f2 = B22, f3 = B23;
            for (int j = 0; j < 64; j++) {
                float h = fmaxf(fmaf(x0, sw0[j], fmaf(x1, sw1[j], b1[j])), 0.0f);
                f0 = fmaf(h, sc[j][0], f0);
                f1 = fmaf(h, sc[j][1], f1);
                f2 = fmaf(h, sc[j][2], f2);
                f3 = fmaf(h, sc[j][3], f3);
            }
            float fx0, fx1;
            lsum += row_tail(x0, x1, f0, f1, f2, f3,
                             y[2 * r], y[2 * r + 1], e[2 * r], e[2 * r + 1],
                             wv00, wv01, wv10, wv11, fx0, fx1);
            ((float*)o4)[2 * r] = fx0;
            ((float*)o4)[2 * r + 1] = fx1;
        }
    }

    // deterministic block tree reduction -> per-block double partial
    sred[t] = (double)lsum;
    __syncthreads();
#pragma unroll
    for (int off = NT / 2; off > 0; off >>= 1) {
        if (t < off) sred[t] += sred[t + off];
        __syncthreads();
    }
    if (t == 0) g_part[blockIdx.x] = sred[0];

    // last-block finalize
    __shared__ bool is_last;
    __threadfence();
    if (t == 0) {
        unsigned prev = atomicAdd(&g_ticket, 1u);
        is_last = (prev == gridDim.x - 1);
    }
    __syncthreads();
    if (is_last) {
        double v = 0.0;
        for (int i = t; i < gridDim.x; i += NT) v += g_part[i];
        sred[t] = v;
        __syncthreads();
#pragma unroll
        for (int off = NT / 2; off > 0; off >>= 1) {
            if (t < off) sred[t] += sred[t + off];
            __syncthreads();
        }
        if (t == 0) {
            out[2 * B] = (float)(0.5 * sred[0] + (double)B * 1.8378770664093453);
            g_ticket = 0;   // reset for next graph replay
        }
    }
}

extern "C" void kernel_launch(void* const* d_in, const int* in_sizes, int n_in,
                              void* d_out, int out_size)
{
    const float* x  = (const float*)d_in[0];
    const float* y  = (const float*)d_in[1];
    const float* e  = (const float*)d_in[2];
    const float* W1 = (const float*)d_in[3];
    const float* b1 = (const float*)d_in[4];
    const float* W2 = (const float*)d_in[5];
    const float* b2 = (const float*)d_in[6];
    const float* Wv = (const float*)d_in[7];
    float* out = (float*)d_out;

    long long B = (long long)in_sizes[0] / 2;
    int nPair = (int)(B / 2);

    int blocks = 304;                      // persistent, 2 blocks/SM
    if (blocks > MAXBLK) blocks = MAXBLK;

    mdn_fused<<<blocks, NT>>>((const float4*)x, (const float4*)y,
                              (const float4*)e, W1, b1, W2, b2, Wv,
                              (float4*)out, out, nPair, B);
}

// round 11
// speedup vs baseline: 2.5341x; 1.0505x over previous
#include <cuda_runtime.h>

// MDN_module — sector-table kernel, conflict-free shared layouts.
// b1 == 0 => all ReLU hinges pass through the origin; MLP is exactly
// piecewise-linear over <=128 angular sectors:
//   f_k(x) = b2_k + A_s[k][0]*x0 + A_s[k][1]*x1
// A_s stored stride-9 floats (bank step coprime with 32 -> no structural
// conflicts). Lookup: diamond pseudo-angle -> int32 bucket table ->
// sorted-boundary refinement. Uniform fallback handles b1 != 0.
// Inputs: x[B,2] y[B,1,2] eps[B,1,2] W1[2,64] b1[64] W2[64,4] b2[4] Wv[2,2]
// Output: fx (2B floats) then logp_y scalar at out[2B].

#define NT 512
#define MAXBLK 2048
#define NBUCKET 512

__device__ double g_part[MAXBLK];
__device__ unsigned g_ticket = 0;

__device__ __forceinline__ float pangle(float x0, float x1) {
    float t = __fdividef(x1, fabsf(x0) + fabsf(x1));
    return (x0 >= 0.0f) ? t : 2.0f - t;
}

// per-row epilogue: returns d0^2/v0 + d1^2/v1 + f2 + f3 ; writes fx0,fx1
__device__ __forceinline__ float row_tail(
    float x0, float x1, float mu0, float mu1, float f2, float f3,
    float y0, float y1, float e0, float e1,
    float wv00, float wv01, float wv10, float wv11,
    float& fx0, float& fx1)
{
    float z0 = fmaf(x0, wv00, x1 * wv10);
    float z1 = fmaf(x0, wv01, x1 * wv11);
    float Vx = fmaf(z0, z0, fmaf(z1, z1, 1e-3f));
    float m0 = fmaf(mu0, wv00, mu1 * wv10);
    float m1 = fmaf(mu0, wv01, mu1 * wv11);
    float Vmu = fmaf(m0, m0, fmaf(m1, m1, 1e-3f));
    float scale = __fdividef(fminf(0.99f * Vx, Vmu), Vmu);  // == beta*Vx - relu(...)
    float ms0 = mu0 * scale;
    float ms1 = mu1 * scale;
    float v0 = __expf(f2);
    float v1 = __expf(f3);
    float r0 = rsqrtf(v0);
    float r1 = rsqrtf(v1);
    fx0 = fmaf(v0 * r0, e0, ms0);
    fx1 = fmaf(v1 * r1, e1, ms1);
    float d0 = y0 - ms0;
    float d1 = y1 - ms1;
    float s = fmaf(d0 * d0, r0 * r0, f2 + f3);   // log v0 + log v1 == f2 + f3 exactly
    s = fmaf(d1 * d1, r1 * r1, s);
    return s;
}

__global__ void __launch_bounds__(NT, 2)
mdn_fused(const float4* __restrict__ x4, const float4* __restrict__ y4,
          const float4* __restrict__ e4,
          const float* __restrict__ W1, const float* __restrict__ b1,
          const float* __restrict__ W2, const float* __restrict__ b2,
          const float* __restrict__ Wv,
          float4* __restrict__ o4, float* __restrict__ out,
          int nPair, long long B)
{
    __shared__ float sBound[129];        // sorted boundary pseudo-angles + INF sentinel
    __shared__ float sAf[128 * 9];       // per-sector affine maps, stride 9 (conflict-free)
    __shared__ int sBkt[NBUCKET];        // bucket -> count of boundaries <= left edge
    __shared__ float sP[128];
    __shared__ float sw0[64], sw1[64];
    __shared__ float sc[64][4];
    __shared__ int sFast;
    __shared__ double swred[NT / 32];

    int t = threadIdx.x;
    if (t == 0) sFast = 1;
    __syncthreads();
    if (t < 64) {
        float w0 = W1[t], w1 = W1[64 + t];
        sw0[t] = w0; sw1[t] = w1;
#pragma unroll
        for (int k = 0; k < 4; k++) sc[t][k] = W2[t * 4 + k];
        float pa = pangle(-w1, w0);      // hinge-line directions (perp to w)
        float pb = pangle(w1, -w0);
        if (!(pa == pa)) pa = -1.0f;     // degenerate w==0: harmless duplicate boundary
        if (!(pb == pb)) pb = -1.0f;
        sP[t] = pa; sP[64 + t] = pb;
        if (b1[t] != 0.0f) sFast = 0;    // benign race, all writers write 0
    }
    __syncthreads();
    if (t < 128) {                        // rank sort (ties broken by index)
        float p = sP[t];
        int rank = 0;
        for (int i = 0; i < 128; i++) {
            float pi = sP[i];
            rank += (pi < p) || (pi == p && i < t);
        }
        sBound[rank] = p;
    }
    if (t == 0) sBound[128] = __int_as_float(0x7F800000);   // +INF sentinel
    __syncthreads();
    if (t < 128) {                        // per-sector affine map from midpoint dir
        float p0 = sBound[t];
        float p1 = (t < 127) ? sBound[t + 1] : (sBound[0] + 4.0f);
        float pm = 0.5f * (p0 + p1);
        if (pm >= 3.0f) pm -= 4.0f;
        float u0, u1;                     // inverse diamond map
        if (pm <= 1.0f) { u1 = pm;        u0 = 1.0f - fabsf(pm); }
        else            { u1 = 2.0f - pm; u0 = fabsf(2.0f - pm) - 1.0f; }
        float A[8] = {0, 0, 0, 0, 0, 0, 0, 0};
        for (int j = 0; j < 64; j++) {
            float w0 = sw0[j], w1 = sw1[j];
            float m = (fmaf(u0, w0, u1 * w1) > 0.0f) ? 1.0f : 0.0f;
#pragma unroll
            for (int k = 0; k < 4; k++) {
                float c = sc[j][k] * m;
                A[2 * k]     = fmaf(c, w0, A[2 * k]);
                A[2 * k + 1] = fmaf(c, w1, A[2 * k + 1]);
            }
        }
#pragma unroll
        for (int k = 0; k < 8; k++) sAf[t * 9 + k] = A[k];
        sAf[t * 9 + 8] = 0.0f;
    }
    __syncthreads();
    for (int q = t; q < NBUCKET; q += NT) {   // bucket table
        float edge = -1.0f + (4.0f / NBUCKET) * (float)q;
        int cnt = 0;
        for (int i = 0; i < 128; i++) cnt += (sBound[i] <= edge) ? 1 : 0;
        sBkt[q] = cnt;
    }
    __syncthreads();

    float B20 = b2[0], B21 = b2[1], B22 = b2[2], B23 = b2[3];
    float wv00 = Wv[0], wv01 = Wv[1], wv10 = Wv[2], wv11 = Wv[3];

    float lsum = 0.0f;
    int gtid = blockIdx.x * NT + t;
    int gstride = gridDim.x * NT;

    if (sFast) {
        for (int i = gtid; i < nPair; i += gstride) {
            float4 xv = __ldcs(&x4[i]);
            float4 yv = __ldcs(&y4[i]);
            float4 ev = __ldcs(&e4[i]);

            // --- two independent lookup chains (halves a and b) ---
            float pa = pangle(xv.x, xv.y);
            float pb = pangle(xv.z, xv.w);
            int qa = min(max((int)((pa + 1.0f) * (NBUCKET / 4.0f)), 0), NBUCKET - 1);
            int qb = min(max((int)((pb + 1.0f) * (NBUCKET / 4.0f)), 0), NBUCKET - 1);
            int ca = sBkt[qa];
            int cb = sBkt[qb];
            while (sBound[ca] <= pa) ca++;       // sentinel bounds c <= 128
            while (sBound[cb] <= pb) cb++;
            int sa = (ca == 0) ? 127 : ca - 1;
            int sb = (cb == 0) ? 127 : cb - 1;
            const float* Aa = &sAf[sa * 9];
            const float* Ab = &sAf[sb * 9];

            float mu0a = fmaf(Aa[0], xv.x, fmaf(Aa[1], xv.y, B20));
            float mu1a = fmaf(Aa[2], xv.x, fmaf(Aa[3], xv.y, B21));
            float f2a  = fmaf(Aa[4], xv.x, fmaf(Aa[5], xv.y, B22));
            float f3a  = fmaf(Aa[6], xv.x, fmaf(Aa[7], xv.y, B23));
            float mu0b = fmaf(Ab[0], xv.z, fmaf(Ab[1], xv.w, B20));
            float mu1b = fmaf(Ab[2], xv.z, fmaf(Ab[3], xv.w, B21));
            float f2b  = fmaf(Ab[4], xv.z, fmaf(Ab[5], xv.w, B22));
            float f3b  = fmaf(Ab[6], xv.z, fmaf(Ab[7], xv.w, B23));

            float4 o;
            lsum += row_tail(xv.x, xv.y, mu0a, mu1a, f2a, f3a, yv.x, yv.y, ev.x, ev.y,
                             wv00, wv01, wv10, wv11, o.x, o.y);
            lsum += row_tail(xv.z, xv.w, mu0b, mu1b, f2b, f3b, yv.z, yv.w, ev.z, ev.w,
                             wv00, wv01, wv10, wv11, o.z, o.w);
            __stcs(&o4[i], o);
        }
        // odd tail row (B even here; safety)
        long long start = 2LL * nPair;
        if (blockIdx.x == 0 && start + t < B) {
            long long r = start + t;
            const float* x = (const float*)x4;
            const float* y = (const float*)y4;
            const float* e = (const float*)e4;
            float x0 = x[2 * r], x1 = x[2 * r + 1];
            float p = pangle(x0, x1);
            int q = min(max((int)((p + 1.0f) * (NBUCKET / 4.0f)), 0), NBUCKET - 1);
            int c = sBkt[q];
            while (sBound[c] <= p) c++;
            int s = (c == 0) ? 127 : c - 1;
            const float* A = &sAf[s * 9];
            float mu0 = fmaf(A[0], x0, fmaf(A[1], x1, B20));
            float mu1 = fmaf(A[2], x0, fmaf(A[3], x1, B21));
            float f2  = fmaf(A[4], x0, fmaf(A[5], x1, B22));
            float f3  = fmaf(A[6], x0, fmaf(A[7], x1, B23));
            float fx0, fx1;
            lsum += row_tail(x0, x1, mu0, mu1, f2, f3,
                             y[2 * r], y[2 * r + 1], e[2 * r], e[2 * r + 1],
                             wv00, wv01, wv10, wv11, fx0, fx1);
            ((float*)o4)[2 * r] = fx0;
            ((float*)o4)[2 * r + 1] = fx1;
        }
    } else {
        // general path (b1 != 0): exact scalar MLP per row. Never taken on this dataset.
        const float* x = (const float*)x4;
        const float* y = (const float*)y4;
        const float* e = (const float*)e4;
        for (long long r = gtid; r < B; r += gstride) {
            float x0 = x[2 * r], x1 = x[2 * r + 1];
            float f0 = B20, f1 = B21, f2 = B22, f3 = B23;
            for (int j = 0; j < 64; j++) {
                float h = fmaxf(fmaf(x0, sw0[j], fmaf(x1, sw1[j], b1[j])), 0.0f);
                f0 = fmaf(h, sc[j][0], f0);
                f1 = fmaf(h, sc[j][1], f1);
                f2 = fmaf(h, sc[j][2], f2);
                f3 = fmaf(h, sc[j][3], f3);
            }
            float fx0, fx1;
            lsum += row_tail(x0, x1, f0, f1, f2, f3,
                             y[2 * r], y[2 * r + 1], e[2 * r], e[2 * r + 1],
                             wv00, wv01, wv10, wv11, fx0, fx1);
            ((float*)o4)[2 * r] = fx0;
            ((float*)o4)[2 * r + 1] = fx1;
        }
    }

    // reduction: double shuffle within warp, then warp partials, then block
    double dsum = (double)lsum;
#pragma unroll
    for (int off = 16; off; off >>= 1)
        dsum += __shfl_xor_sync(0xffffffffu, dsum, off);
    if ((t & 31) == 0) swred[t >> 5] = dsum;
    __syncthreads();
    if (t < 32) {
        double v = (t < NT / 32) ? swred[t] : 0.0;
#pragma unroll
        for (int off = 8; off; off >>= 1)
            v += __shfl_xor_sync(0xffffffffu, v, off);
        if (t == 0) g_part[blockIdx.x] = v;
    }

    // last-block finalize
    __shared__ bool is_last;
    __threadfence();
    if (t == 0) {
        unsigned prev = atomicAdd(&g_ticket, 1u);
        is_last = (prev == gridDim.x - 1);
    }
    __syncthreads();
    if (is_last) {
        double v = 0.0;
        for (int i = t; i < gridDim.x; i += NT) v += g_part[i];
#pragma unroll
        for (int off = 16; off; off >>= 1)
            v += __shfl_xor_sync(0xffffffffu, v, off);
        if ((t & 31) == 0) swred[t >> 5] = v;
        __syncthreads();
        if (t < 32) {
            double w = (t < NT / 32) ? swred[t] : 0.0;
#pragma unroll
            for (int off = 8; off; off >>= 1)
                w += __shfl_xor_sync(0xffffffffu, w, off);
            if (t == 0) {
                out[2 * B] = (float)(0.5 * w + (double)B * 1.8378770664093453);
                g_ticket = 0;   // reset for next graph replay
            }
        }
    }
}

extern "C" void kernel_launch(void* const* d_in, const int* in_sizes, int n_in,
                              void* d_out, int out_size)
{
    const float* x  = (const float*)d_in[0];
    const float* y  = (const float*)d_in[1];
    const float* e  = (const float*)d_in[2];
    const float* W1 = (const float*)d_in[3];
    const float* b1 = (const float*)d_in[4];
    const float* W2 = (const float*)d_in[5];
    const float* b2 = (const float*)d_in[6];
    const float* Wv = (const float*)d_in[7];
    float* out = (float*)d_out;

    long long B = (long long)in_sizes[0] / 2;
    int nPair = (int)(B / 2);

    int blocks = 304;                    // persistent, 2 blocks/SM
    if (blocks > MAXBLK) blocks = MAXBLK;

    mdn_fused<<<blocks, NT>>>((const float4*)x, (const float4*)y,
                              (const float4*)e, W1, b1, W2, b2, Wv,
                              (float4*)out, out, nPair, B);
}